// round 5
// baseline (speedup 1.0000x reference)
#include <cuda_runtime.h>
#include <math.h>

// ---------------- problem constants ----------------------------------------
#define T_LEN   64000
#define B_SZ    2
#define NS      3999
#define NF      3999
#define BS_TOT  (B_SZ * NS)        // 7998
#define HFAST   32
#define ROWS    16                 // sequences per CTA
#define NCTA_SLOW ((BS_TOT + ROWS - 1) / ROWS)   // 500

// smem layout (floats):
//   seq  [32][64][16]         32768
//   wTih [64][196]            12544   (u-major transposed)
//   wThh [64][196]            12544
#define SEQ_F   (32 * 64 * 16)
#define WT_STR  196
#define WT_F    (64 * WT_STR)
#define OFF_WIH SEQ_F
#define OFF_WHH (SEQ_F + WT_F)
#define SMEM_FLOATS (SEQ_F + 2 * WT_F)
#define SMEM_BYTES  (SMEM_FLOATS * 4)            // 231424

// ---------------- device scratch --------------------------------------------
__device__ float d_A[BS_TOT * HFAST];
__device__ float d_G[BS_TOT * HFAST];
__device__ float d_S[BS_TOT * 32];

// ---------------- f32x2 helpers ---------------------------------------------
typedef unsigned long long u64;

__device__ __forceinline__ u64 pack2(float x, float y) {
    u64 r; asm("mov.b64 %0,{%1,%2};" : "=l"(r) : "f"(x), "f"(y)); return r;
}
__device__ __forceinline__ void unpack2(u64 v, float& x, float& y) {
    asm("mov.b64 {%0,%1},%2;" : "=f"(x), "=f"(y) : "l"(v));
}
__device__ __forceinline__ void ffma2(u64& d, u64 a, u64 b) {
    asm("fma.rn.f32x2 %0,%1,%2,%0;" : "+l"(d) : "l"(a), "l"(b));
}

__device__ __forceinline__ float sigmoidf_(float x) {
    return __fdividef(1.0f, 1.0f + __expf(-x));
}
__device__ __forceinline__ float tanhf_(float x) {
    float e = __expf(-2.0f * fabsf(x));
    float t = __fdividef(1.0f - e, 1.0f + e);
    return copysignf(t, x);
}
__device__ __forceinline__ float gatefn(float ar, float az, float an, float ah, float hp) {
    float r = sigmoidf_(ar);
    float z = sigmoidf_(az);
    float n = tanhf_(an + r * ah);
    return z * (hp - n) + n;
}

// ---------------- slow path --------------------------------------------------
__global__ void __launch_bounds__(256, 1) slow_kernel(
    const float* __restrict__ x,
    const float* __restrict__ siW,  const float* __restrict__ sib,
    const float* __restrict__ Wih,  const float* __restrict__ Whh,
    const float* __restrict__ bih,  const float* __restrict__ bhh,
    const float* __restrict__ soW,  const float* __restrict__ sob,
    const float* __restrict__ s2sW, const float* __restrict__ s2sb)
{
    extern __shared__ float sm[];
    float* seq  = sm;              // [t][k][row]
    float* wih  = sm + OFF_WIH;    // [u][g*64+k] transposed, stride 196
    float* whh  = sm + OFF_WHH;
    float* xw   = wih;             // overlay: x windows during init only

    const int tid = threadIdx.x;
    // lane remap: 4 lanes share one hidden unit u, each owns a 4-row quarter.
    // per-warp: 8 distinct u (weight LDS = 1 wavefront), 4 quarters of 64B seq.
    const int u   = tid >> 2;      // 0..63
    const int q   = tid & 3;       // 0..3
    const int r0  = q * 4;
    const int g0  = blockIdx.x * ROWS;
    const int u196 = u * WT_STR;

    // ---- x windows into xw (weight region, pre-weights): xw[r][t] -----------
    for (int i = tid; i < ROWS * 32; i += 256) {
        int r = i >> 5, t = i & 31;
        int g = g0 + r;
        float v = 0.0f;
        if (g < BS_TOT) {
            int b = g / NS;
            int s = g - b * NS;
            v = x[b * T_LEN + s * 16 + t];
        }
        xw[i] = v;
    }
    __syncthreads();

    // ---- layer-0 input: seq[t][k][r] = relu(xw*W+b) --------------------------
    for (int i = tid; i < SEQ_F; i += 256) {
        int r = i & 15;
        int k = (i >> 4) & 63;
        int t = i >> 10;
        seq[i] = fmaxf(xw[r * 32 + t] * __ldg(&siW[k]) + __ldg(&sib[k]), 0.0f);
    }

    // ---- 4 GRU layers ---------------------------------------------------------
    for (int l = 0; l < 4; ++l) {
        const float* gW = Wih + l * 12288;
        const float* gU = Whh + l * 12288;
        __syncthreads();   // prior reads of wih/whh (or xw / layer-0 writes) done
        for (int i = tid; i < 12288; i += 256) {
            int k = i / 192, j = i - k * 192;
            int g = j >> 6, uu = j & 63;
            wih[uu * WT_STR + g * 64 + k] = gW[i];
            whh[uu * WT_STR + g * 64 + k] = gU[i];
        }
        const float b_r  = __ldg(&bih[l*192 + u])       + __ldg(&bhh[l*192 + u]);
        const float b_z  = __ldg(&bih[l*192 + 64 + u])  + __ldg(&bhh[l*192 + 64 + u]);
        const float b_xn = __ldg(&bih[l*192 + 128 + u]);
        const float b_hn = __ldg(&bhh[l*192 + 128 + u]);
        const u64 b2r = pack2(b_r,  b_r);
        const u64 b2z = pack2(b_z,  b_z);
        const u64 b2n = pack2(b_xn, b_xn);
        const u64 b2h = pack2(b_hn, b_hn);
        __syncthreads();

        float hp[4] = {0.f, 0.f, 0.f, 0.f};

        for (int t = 0; t < 32; ++t) {
            u64 ar[2] = {b2r, b2r};
            u64 az[2] = {b2z, b2z};
            u64 an[2] = {b2n, b2n};
            u64 ah[2] = {b2h, b2h};

            // ---- Wih GEMM: reads seq[t] (relu'd prev-layer output) ----------
            {
                const float* st = seq + t * 1024 + r0;
                #pragma unroll 4
                for (int k0 = 0; k0 < 64; k0 += 4) {
                    float4 wr = *(const float4*)(wih + u196 + k0);
                    float4 wz = *(const float4*)(wih + u196 + 64 + k0);
                    float4 wn = *(const float4*)(wih + u196 + 128 + k0);
                    const float* wrp = &wr.x;
                    const float* wzp = &wz.x;
                    const float* wnp = &wn.x;
                    #pragma unroll
                    for (int j = 0; j < 4; ++j) {
                        ulonglong2 s = *(const ulonglong2*)(st + (k0 + j) * 16);
                        u64 w2;
                        w2 = pack2(wrp[j], wrp[j]);
                        ffma2(ar[0], s.x, w2); ffma2(ar[1], s.y, w2);
                        w2 = pack2(wzp[j], wzp[j]);
                        ffma2(az[0], s.x, w2); ffma2(az[1], s.y, w2);
                        w2 = pack2(wnp[j], wnp[j]);
                        ffma2(an[0], s.x, w2); ffma2(an[1], s.y, w2);
                    }
                }
            }
            // ---- Whh GEMM: reads seq[t-1] (pre-relu h_{t-1}) -----------------
            if (t > 0) {
                const float* sp = seq + (t - 1) * 1024 + r0;
                #pragma unroll 4
                for (int k0 = 0; k0 < 64; k0 += 4) {
                    float4 wr = *(const float4*)(whh + u196 + k0);
                    float4 wz = *(const float4*)(whh + u196 + 64 + k0);
                    float4 wn = *(const float4*)(whh + u196 + 128 + k0);
                    const float* wrp = &wr.x;
                    const float* wzp = &wz.x;
                    const float* wnp = &wn.x;
                    #pragma unroll
                    for (int j = 0; j < 4; ++j) {
                        ulonglong2 s = *(const ulonglong2*)(sp + (k0 + j) * 16);
                        u64 w2;
                        w2 = pack2(wrp[j], wrp[j]);
                        ffma2(ar[0], s.x, w2); ffma2(ar[1], s.y, w2);
                        w2 = pack2(wzp[j], wzp[j]);
                        ffma2(az[0], s.x, w2); ffma2(az[1], s.y, w2);
                        w2 = pack2(wnp[j], wnp[j]);
                        ffma2(ah[0], s.x, w2); ffma2(ah[1], s.y, w2);
                    }
                }
            }
            __syncthreads();   // all reads of seq[t], seq[t-1] complete

            float hn[4];
            float zr[4], zz[4], zn[4], zh[4];
            unpack2(ar[0], zr[0], zr[1]); unpack2(ar[1], zr[2], zr[3]);
            unpack2(az[0], zz[0], zz[1]); unpack2(az[1], zz[2], zz[3]);
            unpack2(an[0], zn[0], zn[1]); unpack2(an[1], zn[2], zn[3]);
            unpack2(ah[0], zh[0], zh[1]); unpack2(ah[1], zh[2], zh[3]);
            #pragma unroll
            for (int i = 0; i < 4; ++i)
                hn[i] = gatefn(zr[i], zz[i], zn[i], zh[i], hp[i]);

            // write pre-relu h_t -> seq[t]; relu(h_{t-1}) -> seq[t-1]
            *(float4*)(seq + t * 1024 + u * 16 + r0) =
                make_float4(hn[0], hn[1], hn[2], hn[3]);
            if (t > 0) {
                *(float4*)(seq + (t - 1) * 1024 + u * 16 + r0) =
                    make_float4(fmaxf(hp[0], 0.f), fmaxf(hp[1], 0.f),
                                fmaxf(hp[2], 0.f), fmaxf(hp[3], 0.f));
            }
            #pragma unroll
            for (int i = 0; i < 4; ++i) hp[i] = hn[i];
            __syncthreads();   // writes visible before next step
        }
        // finalize: relu(h_31) -> seq[31]
        *(float4*)(seq + 31 * 1024 + u * 16 + r0) =
            make_float4(fmaxf(hp[0], 0.f), fmaxf(hp[1], 0.f),
                        fmaxf(hp[2], 0.f), fmaxf(hp[3], 0.f));
    }
    __syncthreads();

    // ---- head: slow_feat = seq[31] @ soW + sob ; eps = sf @ s2sW + s2sb ------
    for (int i = tid; i < 64 * 64; i += 256) {
        wih[i] = soW[i];
        whh[i] = s2sW[i];
    }
    __syncthreads();

    {
        float acc[4];
        float bb = __ldg(&sob[u]);
        #pragma unroll
        for (int i = 0; i < 4; ++i) acc[i] = bb;
        const float* sl = seq + 31 * 1024 + r0;   // already relu'd
        #pragma unroll 8
        for (int k = 0; k < 64; ++k) {
            float4 v = *(const float4*)(sl + k * 16);
            float w = wih[k * 64 + u];
            acc[0] += v.x * w; acc[1] += v.y * w;
            acc[2] += v.z * w; acc[3] += v.w * w;
        }
        // slow_feat -> seq[0] region as [c=u][row]
        *(float4*)(seq + u * 16 + r0) = make_float4(acc[0], acc[1], acc[2], acc[3]);
    }
    __syncthreads();

    {
        float acc[4];
        float bb = __ldg(&s2sb[u]);
        #pragma unroll
        for (int i = 0; i < 4; ++i) acc[i] = bb;
        #pragma unroll 8
        for (int k = 0; k < 64; ++k) {
            float4 v = *(const float4*)(seq + k * 16 + r0);
            float w = whh[k * 64 + u];
            acc[0] += v.x * w; acc[1] += v.y * w;
            acc[2] += v.z * w; acc[3] += v.w * w;
        }
        #pragma unroll
        for (int i = 0; i < 4; ++i) {
            int g = g0 + r0 + i;
            if (g < BS_TOT) {
                if (u < HFAST) d_A[g * HFAST + u] = sigmoidf_(acc[i]);
                else           d_G[g * HFAST + (u - HFAST)] = acc[i];
            }
        }
    }
}

// ---------------- fast path: diagonal SSM, warp per frame -------------------
__global__ void __launch_bounds__(256) fast_kernel(
    const float* __restrict__ x,
    const float* __restrict__ finW, const float* __restrict__ finb,
    const float* __restrict__ foutW, const float* __restrict__ foutb)
{
    int w = (blockIdx.x * blockDim.x + threadIdx.x) >> 5;
    int h = threadIdx.x & 31;
    if (w >= BS_TOT) return;
    int b = w / NF;
    int f = w - b * NF;

    float A  = d_A[w * HFAST + h];
    float G  = d_G[w * HFAST + h];
    float fw = __ldg(&finW[h]);
    float fb = __ldg(&finb[h]);
    float fo = __ldg(&foutW[h]);
    float fob = __ldg(&foutb[0]);

    const float* xp = x + b * T_LEN + f * 16;
    float hs = 0.f;
    #pragma unroll
    for (int t = 0; t < 32; ++t) {
        float e = (xp[t] * fw + fb) * G;
        hs = A * hs + e;
        float y = hs * fo;
        #pragma unroll
        for (int m = 16; m; m >>= 1) y += __shfl_xor_sync(0xffffffffu, y, m);
        if (h == t) d_S[w * 32 + t] = y + fob;
    }
}

// ---------------- overlap-add gather -----------------------------------------
__global__ void __launch_bounds__(256) oadd_kernel(float* __restrict__ out)
{
    int idx = blockIdx.x * blockDim.x + threadIdx.x;
    if (idx >= B_SZ * T_LEN) return;
    int b = idx / T_LEN;
    int i = idx - b * T_LEN;
    int f1 = i >> 4;
    int j  = i & 15;
    float v = 0.f;
    if (f1 < NF) v += d_S[(b * NF + f1) * 32 + j];
    if (f1 >= 1) v += d_S[(b * NF + f1 - 1) * 32 + j + 16];
    out[idx] = v;
}

// ---------------- launch -------------------------------------------------------
extern "C" void kernel_launch(void* const* d_in, const int* in_sizes, int n_in,
                              void* d_out, int out_size)
{
    const float* x    = (const float*)d_in[0];
    const float* siW  = (const float*)d_in[1];
    const float* sib  = (const float*)d_in[2];
    const float* Wih  = (const float*)d_in[3];
    const float* Whh  = (const float*)d_in[4];
    const float* bih  = (const float*)d_in[5];
    const float* bhh  = (const float*)d_in[6];
    const float* soW  = (const float*)d_in[7];
    const float* sob  = (const float*)d_in[8];
    const float* s2sW = (const float*)d_in[9];
    const float* s2sb = (const float*)d_in[10];
    const float* finW = (const float*)d_in[11];
    const float* finb = (const float*)d_in[12];
    const float* foW  = (const float*)d_in[13];
    const float* fob  = (const float*)d_in[14];
    float* out = (float*)d_out;

    cudaFuncSetAttribute(slow_kernel,
                         cudaFuncAttributeMaxDynamicSharedMemorySize, SMEM_BYTES);

    slow_kernel<<<NCTA_SLOW, 256, SMEM_BYTES>>>(
        x, siW, sib, Wih, Whh, bih, bhh, soW, sob, s2sW, s2sb);

    int fast_blocks = (BS_TOT * 32 + 255) / 256;
    fast_kernel<<<fast_blocks, 256>>>(x, finW, finb, foW, fob);

    int oadd_blocks = (B_SZ * T_LEN + 255) / 256;
    oadd_kernel<<<oadd_blocks, 256>>>(out);
}

// round 6
// speedup vs baseline: 1.0007x; 1.0007x over previous
#include <cuda_runtime.h>
#include <math.h>

// ---------------- problem constants ----------------------------------------
#define T_LEN   64000
#define B_SZ    2
#define NS      3999
#define NF      3999
#define BS_TOT  (B_SZ * NS)        // 7998
#define HFAST   32
#define ROWS    16                 // sequences per CTA
#define NCTA_SLOW ((BS_TOT + ROWS - 1) / ROWS)   // 500

// smem layout (floats):
//   seq  [32][64][16]         32768
//   wTih [64][196]            12544   (u-major transposed)
//   wThh [64][196]            12544
#define SEQ_F   (32 * 64 * 16)
#define WT_STR  196
#define WT_F    (64 * WT_STR)
#define OFF_WIH SEQ_F
#define OFF_WHH (SEQ_F + WT_F)
#define SMEM_FLOATS (SEQ_F + 2 * WT_F)
#define SMEM_BYTES  (SMEM_FLOATS * 4)            // 231424

// ---------------- device scratch --------------------------------------------
__device__ float d_A[BS_TOT * HFAST];
__device__ float d_G[BS_TOT * HFAST];
__device__ float d_S[BS_TOT * 32];

// ---------------- f32x2 helpers ---------------------------------------------
typedef unsigned long long u64;

__device__ __forceinline__ u64 pack2(float x, float y) {
    u64 r; asm("mov.b64 %0,{%1,%2};" : "=l"(r) : "f"(x), "f"(y)); return r;
}
__device__ __forceinline__ void unpack2(u64 v, float& x, float& y) {
    asm("mov.b64 {%0,%1},%2;" : "=f"(x), "=f"(y) : "l"(v));
}
__device__ __forceinline__ void ffma2(u64& d, u64 a, u64 b) {
    asm("fma.rn.f32x2 %0,%1,%2,%0;" : "+l"(d) : "l"(a), "l"(b));
}

__device__ __forceinline__ float sigmoidf_(float x) {
    return __fdividef(1.0f, 1.0f + __expf(-x));
}
__device__ __forceinline__ float tanhf_(float x) {
    float e = __expf(-2.0f * fabsf(x));
    float t = __fdividef(1.0f - e, 1.0f + e);
    return copysignf(t, x);
}
__device__ __forceinline__ float gatefn(float ar, float az, float an, float ah, float hp) {
    float r = sigmoidf_(ar);
    float z = sigmoidf_(az);
    float n = tanhf_(an + r * ah);
    return z * (hp - n) + n;
}

// ---------------- slow path --------------------------------------------------
__global__ void __launch_bounds__(256, 1) slow_kernel(
    const float* __restrict__ x,
    const float* __restrict__ siW,  const float* __restrict__ sib,
    const float* __restrict__ Wih,  const float* __restrict__ Whh,
    const float* __restrict__ bih,  const float* __restrict__ bhh,
    const float* __restrict__ soW,  const float* __restrict__ sob,
    const float* __restrict__ s2sW, const float* __restrict__ s2sb)
{
    extern __shared__ float sm[];
    float* seq  = sm;              // [t][k][row]
    float* wih  = sm + OFF_WIH;    // [u][g*64+k] transposed, stride 196
    float* whh  = sm + OFF_WHH;
    float* xw   = wih;             // overlay: x windows during init only

    const int tid = threadIdx.x;
    // lane remap: 4 lanes share one hidden unit u, each owns a 4-row quarter.
    // per-warp: 8 distinct u (weight LDS = 1 wavefront), 4 quarters of 64B seq.
    const int u   = tid >> 2;      // 0..63
    const int q   = tid & 3;       // 0..3
    const int r0  = q * 4;
    const int g0  = blockIdx.x * ROWS;
    const int u196 = u * WT_STR;

    // ---- x windows into xw (weight region, pre-weights): xw[r][t] -----------
    for (int i = tid; i < ROWS * 32; i += 256) {
        int r = i >> 5, t = i & 31;
        int g = g0 + r;
        float v = 0.0f;
        if (g < BS_TOT) {
            int b = g / NS;
            int s = g - b * NS;
            v = x[b * T_LEN + s * 16 + t];
        }
        xw[i] = v;
    }
    __syncthreads();

    // ---- layer-0 input: seq[t][k][r] = relu(xw*W+b) --------------------------
    for (int i = tid; i < SEQ_F; i += 256) {
        int r = i & 15;
        int k = (i >> 4) & 63;
        int t = i >> 10;
        seq[i] = fmaxf(xw[r * 32 + t] * __ldg(&siW[k]) + __ldg(&sib[k]), 0.0f);
    }

    // ---- 4 GRU layers ---------------------------------------------------------
    for (int l = 0; l < 4; ++l) {
        const float* gW = Wih + l * 12288;
        const float* gU = Whh + l * 12288;
        __syncthreads();   // prior reads of wih/whh (or xw / layer-0 writes) done
        for (int i = tid; i < 12288; i += 256) {
            int k = i / 192, j = i - k * 192;
            int g = j >> 6, uu = j & 63;
            wih[uu * WT_STR + g * 64 + k] = gW[i];
            whh[uu * WT_STR + g * 64 + k] = gU[i];
        }
        const float b_r  = __ldg(&bih[l*192 + u])       + __ldg(&bhh[l*192 + u]);
        const float b_z  = __ldg(&bih[l*192 + 64 + u])  + __ldg(&bhh[l*192 + 64 + u]);
        const float b_xn = __ldg(&bih[l*192 + 128 + u]);
        const float b_hn = __ldg(&bhh[l*192 + 128 + u]);
        const u64 b2r = pack2(b_r,  b_r);
        const u64 b2z = pack2(b_z,  b_z);
        const u64 b2n = pack2(b_xn, b_xn);
        const u64 b2h = pack2(b_hn, b_hn);
        __syncthreads();

        float hp[4] = {0.f, 0.f, 0.f, 0.f};

        for (int t = 0; t < 32; ++t) {
            u64 ar[2] = {b2r, b2r};
            u64 az[2] = {b2z, b2z};
            u64 an[2] = {b2n, b2n};
            u64 ah[2] = {b2h, b2h};

            // ---- Wih GEMM: reads seq[t] (relu'd prev-layer output) ----------
            {
                const float* st = seq + t * 1024 + r0;
                #pragma unroll 4
                for (int k0 = 0; k0 < 64; k0 += 4) {
                    float4 wr = *(const float4*)(wih + u196 + k0);
                    float4 wz = *(const float4*)(wih + u196 + 64 + k0);
                    float4 wn = *(const float4*)(wih + u196 + 128 + k0);
                    const float* wrp = &wr.x;
                    const float* wzp = &wz.x;
                    const float* wnp = &wn.x;
                    #pragma unroll
                    for (int j = 0; j < 4; ++j) {
                        ulonglong2 s = *(const ulonglong2*)(st + (k0 + j) * 16);
                        u64 w2;
                        w2 = pack2(wrp[j], wrp[j]);
                        ffma2(ar[0], s.x, w2); ffma2(ar[1], s.y, w2);
                        w2 = pack2(wzp[j], wzp[j]);
                        ffma2(az[0], s.x, w2); ffma2(az[1], s.y, w2);
                        w2 = pack2(wnp[j], wnp[j]);
                        ffma2(an[0], s.x, w2); ffma2(an[1], s.y, w2);
                    }
                }
            }
            // ---- Whh GEMM: reads seq[t-1] (pre-relu h_{t-1}) -----------------
            if (t > 0) {
                const float* sp = seq + (t - 1) * 1024 + r0;
                #pragma unroll 4
                for (int k0 = 0; k0 < 64; k0 += 4) {
                    float4 wr = *(const float4*)(whh + u196 + k0);
                    float4 wz = *(const float4*)(whh + u196 + 64 + k0);
                    float4 wn = *(const float4*)(whh + u196 + 128 + k0);
                    const float* wrp = &wr.x;
                    const float* wzp = &wz.x;
                    const float* wnp = &wn.x;
                    #pragma unroll
                    for (int j = 0; j < 4; ++j) {
                        ulonglong2 s = *(const ulonglong2*)(sp + (k0 + j) * 16);
                        u64 w2;
                        w2 = pack2(wrp[j], wrp[j]);
                        ffma2(ar[0], s.x, w2); ffma2(ar[1], s.y, w2);
                        w2 = pack2(wzp[j], wzp[j]);
                        ffma2(az[0], s.x, w2); ffma2(az[1], s.y, w2);
                        w2 = pack2(wnp[j], wnp[j]);
                        ffma2(ah[0], s.x, w2); ffma2(ah[1], s.y, w2);
                    }
                }
            }
            __syncthreads();   // all reads of seq[t], seq[t-1] complete

            float hn[4];
            float zr[4], zz[4], zn[4], zh[4];
            unpack2(ar[0], zr[0], zr[1]); unpack2(ar[1], zr[2], zr[3]);
            unpack2(az[0], zz[0], zz[1]); unpack2(az[1], zz[2], zz[3]);
            unpack2(an[0], zn[0], zn[1]); unpack2(an[1], zn[2], zn[3]);
            unpack2(ah[0], zh[0], zh[1]); unpack2(ah[1], zh[2], zh[3]);
            #pragma unroll
            for (int i = 0; i < 4; ++i)
                hn[i] = gatefn(zr[i], zz[i], zn[i], zh[i], hp[i]);

            // write pre-relu h_t -> seq[t]; relu(h_{t-1}) -> seq[t-1]
            *(float4*)(seq + t * 1024 + u * 16 + r0) =
                make_float4(hn[0], hn[1], hn[2], hn[3]);
            if (t > 0) {
                *(float4*)(seq + (t - 1) * 1024 + u * 16 + r0) =
                    make_float4(fmaxf(hp[0], 0.f), fmaxf(hp[1], 0.f),
                                fmaxf(hp[2], 0.f), fmaxf(hp[3], 0.f));
            }
            #pragma unroll
            for (int i = 0; i < 4; ++i) hp[i] = hn[i];
            __syncthreads();   // writes visible before next step
        }
        // finalize: relu(h_31) -> seq[31]
        *(float4*)(seq + 31 * 1024 + u * 16 + r0) =
            make_float4(fmaxf(hp[0], 0.f), fmaxf(hp[1], 0.f),
                        fmaxf(hp[2], 0.f), fmaxf(hp[3], 0.f));
    }
    __syncthreads();

    // ---- head: slow_feat = seq[31] @ soW + sob ; eps = sf @ s2sW + s2sb ------
    for (int i = tid; i < 64 * 64; i += 256) {
        wih[i] = soW[i];
        whh[i] = s2sW[i];
    }
    __syncthreads();

    {
        float acc[4];
        float bb = __ldg(&sob[u]);
        #pragma unroll
        for (int i = 0; i < 4; ++i) acc[i] = bb;
        const float* sl = seq + 31 * 1024 + r0;   // already relu'd
        #pragma unroll 8
        for (int k = 0; k < 64; ++k) {
            float4 v = *(const float4*)(sl + k * 16);
            float w = wih[k * 64 + u];
            acc[0] += v.x * w; acc[1] += v.y * w;
            acc[2] += v.z * w; acc[3] += v.w * w;
        }
        // slow_feat -> seq[0] region as [c=u][row]
        *(float4*)(seq + u * 16 + r0) = make_float4(acc[0], acc[1], acc[2], acc[3]);
    }
    __syncthreads();

    {
        float acc[4];
        float bb = __ldg(&s2sb[u]);
        #pragma unroll
        for (int i = 0; i < 4; ++i) acc[i] = bb;
        #pragma unroll 8
        for (int k = 0; k < 64; ++k) {
            float4 v = *(const float4*)(seq + k * 16 + r0);
            float w = whh[k * 64 + u];
            acc[0] += v.x * w; acc[1] += v.y * w;
            acc[2] += v.z * w; acc[3] += v.w * w;
        }
        #pragma unroll
        for (int i = 0; i < 4; ++i) {
            int g = g0 + r0 + i;
            if (g < BS_TOT) {
                if (u < HFAST) d_A[g * HFAST + u] = sigmoidf_(acc[i]);
                else           d_G[g * HFAST + (u - HFAST)] = acc[i];
            }
        }
    }
}

// ---------------- fast path: diagonal SSM, warp per frame -------------------
__global__ void __launch_bounds__(256) fast_kernel(
    const float* __restrict__ x,
    const float* __restrict__ finW, const float* __restrict__ finb,
    const float* __restrict__ foutW, const float* __restrict__ foutb)
{
    int w = (blockIdx.x * blockDim.x + threadIdx.x) >> 5;
    int h = threadIdx.x & 31;
    if (w >= BS_TOT) return;
    int b = w / NF;
    int f = w - b * NF;

    float A  = d_A[w * HFAST + h];
    float G  = d_G[w * HFAST + h];
    float fw = __ldg(&finW[h]);
    float fb = __ldg(&finb[h]);
    float fo = __ldg(&foutW[h]);
    float fob = __ldg(&foutb[0]);

    const float* xp = x + b * T_LEN + f * 16;
    float hs = 0.f;
    #pragma unroll
    for (int t = 0; t < 32; ++t) {
        float e = (xp[t] * fw + fb) * G;
        hs = A * hs + e;
        float y = hs * fo;
        #pragma unroll
        for (int m = 16; m; m >>= 1) y += __shfl_xor_sync(0xffffffffu, y, m);
        if (h == t) d_S[w * 32 + t] = y + fob;
    }
}

// ---------------- overlap-add gather -----------------------------------------
__global__ void __launch_bounds__(256) oadd_kernel(float* __restrict__ out)
{
    int idx = blockIdx.x * blockDim.x + threadIdx.x;
    if (idx >= B_SZ * T_LEN) return;
    int b = idx / T_LEN;
    int i = idx - b * T_LEN;
    int f1 = i >> 4;
    int j  = i & 15;
    float v = 0.f;
    if (f1 < NF) v += d_S[(b * NF + f1) * 32 + j];
    if (f1 >= 1) v += d_S[(b * NF + f1 - 1) * 32 + j + 16];
    out[idx] = v;
}

// ---------------- launch -------------------------------------------------------
extern "C" void kernel_launch(void* const* d_in, const int* in_sizes, int n_in,
                              void* d_out, int out_size)
{
    const float* x    = (const float*)d_in[0];
    const float* siW  = (const float*)d_in[1];
    const float* sib  = (const float*)d_in[2];
    const float* Wih  = (const float*)d_in[3];
    const float* Whh  = (const float*)d_in[4];
    const float* bih  = (const float*)d_in[5];
    const float* bhh  = (const float*)d_in[6];
    const float* soW  = (const float*)d_in[7];
    const float* sob  = (const float*)d_in[8];
    const float* s2sW = (const float*)d_in[9];
    const float* s2sb = (const float*)d_in[10];
    const float* finW = (const float*)d_in[11];
    const float* finb = (const float*)d_in[12];
    const float* foW  = (const float*)d_in[13];
    const float* fob  = (const float*)d_in[14];
    float* out = (float*)d_out;

    cudaFuncSetAttribute(slow_kernel,
                         cudaFuncAttributeMaxDynamicSharedMemorySize, SMEM_BYTES);

    slow_kernel<<<NCTA_SLOW, 256, SMEM_BYTES>>>(
        x, siW, sib, Wih, Whh, bih, bhh, soW, sob, s2sW, s2sb);

    int fast_blocks = (BS_TOT * 32 + 255) / 256;
    fast_kernel<<<fast_blocks, 256>>>(x, finW, finb, foW, fob);

    int oadd_blocks = (B_SZ * T_LEN + 255) / 256;
    oadd_kernel<<<oadd_blocks, 256>>>(out);
}

// round 9
// speedup vs baseline: 2.3553x; 2.3536x over previous
#include <cuda_runtime.h>
#include <cuda_bf16.h>
#include <math.h>
#include <stdint.h>

#define T_LEN 64000
#define B_SZ  2
#define NS    3999
#define NF    3999
#define BS_TOT (B_SZ*NS)
#define HFAST 32
#define NCTA  126
#define MROWS 64
#define TILE_U4 1152            // uint4 per layer-IO tile (hi 576 + lo 576)

// smem byte offsets
#define SM_X   0                // X [64][72] bf16 hi ; +9216 lo
#define SM_H   18432            // H [64][72] bf16 hi ; +9216 lo
#define SM_WI  36864            // Wih^T [192][72] bf16 hi ; +27648 lo
#define SM_WH  92160            // Whh^T same
#define SM_BIAS 147456          // 256 floats
#define SMEM_SZ 148480

__device__ uint4 d_lay[2][(size_t)NCTA*32*TILE_U4];
__device__ float d_W2[64*64];
__device__ float d_b2[64];
__device__ float d_A[BS_TOT*HFAST];
__device__ float d_G[BS_TOT*HFAST];
__device__ float d_S[BS_TOT*32];

typedef unsigned uu;

__device__ __forceinline__ uu s2u(const void* p){
    uu a; asm("{.reg .u64 t; cvta.to.shared.u64 t,%1; cvt.u32.u64 %0,t;}":"=r"(a):"l"(p)); return a;
}
__device__ __forceinline__ void ldsm4(uu* r, uu a){
    asm volatile("ldmatrix.sync.aligned.m8n8.x4.shared.b16 {%0,%1,%2,%3},[%4];"
        :"=r"(r[0]),"=r"(r[1]),"=r"(r[2]),"=r"(r[3]):"r"(a));
}
__device__ __forceinline__ void ldsm2(uu* r, uu a){
    asm volatile("ldmatrix.sync.aligned.m8n8.x2.shared.b16 {%0,%1},[%2];"
        :"=r"(r[0]),"=r"(r[1]):"r"(a));
}
__device__ __forceinline__ void mma16816(float* d, const uu* a, const uu* b){
    asm volatile("mma.sync.aligned.m16n8k16.row.col.f32.bf16.bf16.f32 "
        "{%0,%1,%2,%3},{%4,%5,%6,%7},{%8,%9},{%0,%1,%2,%3};"
        :"+f"(d[0]),"+f"(d[1]),"+f"(d[2]),"+f"(d[3])
        :"r"(a[0]),"r"(a[1]),"r"(a[2]),"r"(a[3]),"r"(b[0]),"r"(b[1]));
}
__device__ __forceinline__ float frcp(float x){
    float r; asm("rcp.approx.f32 %0,%1;":"=f"(r):"f"(x)); return r;
}
__device__ __forceinline__ void splitw(float a, float b, uu& hi, uu& lo){
    __nv_bfloat16 A=__float2bfloat16(a), B=__float2bfloat16(b);
    __nv_bfloat162 H; H.x=A; H.y=B; hi=*(uu*)&H;
    __nv_bfloat162 L=__floats2bfloat162_rn(a-__bfloat162float(A), b-__bfloat162float(B));
    lo=*(uu*)&L;
}
__device__ __forceinline__ float sigm(float x){ return frcp(1.0f+__expf(fminf(-x,30.f))); }

// ---- prep: layer-0 input relu(x*siW+sib) -> bf16 hi/lo tiles -----------------
__global__ void __launch_bounds__(256) prep_kernel(
    const float* __restrict__ x, const float* __restrict__ siW, const float* __restrict__ sib)
{
    int cta=blockIdx.x>>5, t=blockIdx.x&31;
    int m=threadIdx.x>>2, c=threadIdx.x&3;
    int g=cta*MROWS+m;
    float xv=0.f;
    if(g<BS_TOT){ int b=g/NS, s=g-b*NS; xv=x[b*T_LEN+s*16+t]; }
    uu* ti=(uu*)(d_lay[0]+(size_t)(cta*32+t)*TILE_U4);
    #pragma unroll
    for(int i=0;i<8;++i){
        int k=c*16+i*2;
        float v0=fmaxf(xv*__ldg(&siW[k])+__ldg(&sib[k]),0.f);
        float v1=fmaxf(xv*__ldg(&siW[k+1])+__ldg(&sib[k+1]),0.f);
        uu hi,lo; splitw(v0,v1,hi,lo);
        ti[m*36+(k>>1)]=hi;
        ti[2304+m*36+(k>>1)]=lo;
    }
}

// ---- slow: mma.sync bf16 hi/lo GRU, 4 layers x 32 steps -----------------------
__global__ void __launch_bounds__(256,1) slow_kernel(
    const float* __restrict__ Wih, const float* __restrict__ Whh,
    const float* __restrict__ bih, const float* __restrict__ bhh)
{
    extern __shared__ unsigned char smc[];
    const int tid=threadIdx.x, w=tid>>5, lane=tid&31;
    const int mw=w&3, uw=w>>2;
    const int r0w=mw*16, u0w=uw*32;
    const int cta=blockIdx.x;
    const uu smb=s2u(smc);
    float* bias=(float*)(smc+SM_BIAS);

    // ldmatrix address components
    const uu arow=(uu)((r0w+(lane&15))*144 + ((lane>>4)&1)*16);   // A: X/H tiles
    const uu brow=(uu)((lane&7)*144 + ((lane>>3)&1)*16);          // B: W tiles

    for(int l=0;l<4;++l){
        const uint4* inb = d_lay[l&1] + (size_t)cta*32*TILE_U4;
        uu* outb = (uu*)(d_lay[(l+1)&1] + (size_t)cta*32*TILE_U4);

        // stage weights transposed [n][k] bf16 hi/lo
        for(int i=tid;i<12288;i+=256){
            int k=i/192, n=i-k*192;
            uu off=(uu)(n*144+k*2);
            float v=Wih[l*12288+i];
            __nv_bfloat16 h=__float2bfloat16(v);
            *(__nv_bfloat16*)(smc+SM_WI+off)=h;
            *(__nv_bfloat16*)(smc+SM_WI+27648+off)=__float2bfloat16(v-__bfloat162float(h));
            v=Whh[l*12288+i];
            h=__float2bfloat16(v);
            *(__nv_bfloat16*)(smc+SM_WH+off)=h;
            *(__nv_bfloat16*)(smc+SM_WH+27648+off)=__float2bfloat16(v-__bfloat162float(h));
        }
        if(tid<128)      bias[tid]=bih[l*192+tid]+bhh[l*192+tid];   // r,z combined
        else if(tid<192) bias[tid]=bih[l*192+tid];                  // xn (cols 128..191)
        else             bias[tid]=bhh[l*192+tid-64];               // hn (cols 128..191)

        // stage X(0)
        { uint4* xs=(uint4*)(smc+SM_X);
          for(int i=tid;i<TILE_U4;i+=256) xs[i]=inb[i]; }
        __syncthreads();

        float hp[4][4];
        #pragma unroll
        for(int c=0;c<4;++c){ hp[c][0]=0.f;hp[c][1]=0.f;hp[c][2]=0.f;hp[c][3]=0.f; }

        #pragma unroll 1
        for(int t=0;t<32;++t){
            float Ar[4][4],Az[4][4],Ax[4][4],Ah[4][4];
            #pragma unroll
            for(int c=0;c<4;++c)
                #pragma unroll
                for(int e=0;e<4;++e){ Ar[c][e]=0.f;Az[c][e]=0.f;Ax[c][e]=0.f;Ah[c][e]=0.f; }

            #pragma unroll
            for(int kt=0;kt<4;++kt){
                uu axh[4],axl[4],ahh[4],ahl[4];
                ldsm4(axh, smb+SM_X+arow+kt*32);
                ldsm4(axl, smb+SM_X+9216+arow+kt*32);
                if(t){
                    ldsm4(ahh, smb+SM_H+arow+kt*32);
                    ldsm4(ahl, smb+SM_H+9216+arow+kt*32);
                }
                #pragma unroll
                for(int ct=0;ct<4;++ct){
                    const uu nR=(uu)((u0w+ct*8)*144);
                    const uu nZ=nR+(uu)(64*144);
                    const uu nN=nR+(uu)(128*144);
                    uu b0[2],b1[2];
                    // r gate: X@Wih_r (+ H@Whh_r)
                    ldsm2(b0, smb+SM_WI+nR+brow+kt*32);
                    ldsm2(b1, smb+SM_WI+27648+nR+brow+kt*32);
                    mma16816(Ar[ct],axh,b0); mma16816(Ar[ct],axh,b1); mma16816(Ar[ct],axl,b0);
                    if(t){
                        ldsm2(b0, smb+SM_WH+nR+brow+kt*32);
                        ldsm2(b1, smb+SM_WH+27648+nR+brow+kt*32);
                        mma16816(Ar[ct],ahh,b0); mma16816(Ar[ct],ahh,b1); mma16816(Ar[ct],ahl,b0);
                    }
                    // z gate
                    ldsm2(b0, smb+SM_WI+nZ+brow+kt*32);
                    ldsm2(b1, smb+SM_WI+27648+nZ+brow+kt*32);
                    mma16816(Az[ct],axh,b0); mma16816(Az[ct],axh,b1); mma16816(Az[ct],axl,b0);
                    if(t){
                        ldsm2(b0, smb+SM_WH+nZ+brow+kt*32);
                        ldsm2(b1, smb+SM_WH+27648+nZ+brow+kt*32);
                        mma16816(Az[ct],ahh,b0); mma16816(Az[ct],ahh,b1); mma16816(Az[ct],ahl,b0);
                    }
                    // xn (Wih only)
                    ldsm2(b0, smb+SM_WI+nN+brow+kt*32);
                    ldsm2(b1, smb+SM_WI+27648+nN+brow+kt*32);
                    mma16816(Ax[ct],axh,b0); mma16816(Ax[ct],axh,b1); mma16816(Ax[ct],axl,b0);
                    // hn (Whh only)
                    if(t){
                        ldsm2(b0, smb+SM_WH+nN+brow+kt*32);
                        ldsm2(b1, smb+SM_WH+27648+nN+brow+kt*32);
                        mma16816(Ah[ct],ahh,b0); mma16816(Ah[ct],ahh,b1); mma16816(Ah[ct],ahl,b0);
                    }
                }
            }

            // prefetch next X tile into registers (gmem, L2-resident)
            uint4 pf[5];
            if(t<31){
                const uint4* nx=inb+(size_t)(t+1)*TILE_U4;
                #pragma unroll
                for(int j=0;j<5;++j){ int idx=tid+j*256; if(idx<TILE_U4) pf[j]=nx[idx]; }
            }

            // gates: fully in registers (m16n8k16 D layout: row=lane/4(+8), col=(lane%4)*2(+1))
            float hv[4][4];
            #pragma unroll
            for(int ct=0;ct<4;++ct){
                const int ue=u0w+ct*8+(lane&3)*2;
                #pragma unroll
                for(int e=0;e<4;++e){
                    const int u=ue+(e&1);
                    float ar=Ar[ct][e]+bias[u];
                    float az=Az[ct][e]+bias[64+u];
                    float ax=Ax[ct][e]+bias[128+u];
                    float ah=Ah[ct][e]+bias[192+u];
                    float tr=__expf(fminf(-ar,30.f));
                    float tz=__expf(fminf(-az,30.f));
                    float q=frcp((1.f+tr)*(1.f+tz));
                    float r=q*(1.f+tz), z=q*(1.f+tr);
                    float wv=ax+r*ah;
                    float tn=__expf(fminf(-2.f*wv,30.f));
                    float n=2.f*frcp(1.f+tn)-1.f;
                    float hn=z*(hp[ct][e]-n)+n;
                    hp[ct][e]=hn; hv[ct][e]=hn;
                }
            }

            __syncthreads();   // S1: all smem reads of step t complete

            const bool wout=(l<3)||(t==31);
            uu* oti=outb+(size_t)t*4608;
            #pragma unroll
            for(int ct=0;ct<4;++ct){
                const int ue=u0w+ct*8+(lane&3)*2;
                const int rA=r0w+(lane>>2);
                uu hi,lo;
                splitw(hv[ct][0],hv[ct][1],hi,lo);
                *(uu*)(smc+SM_H+rA*144+ue*2)=hi;
                *(uu*)(smc+SM_H+9216+rA*144+ue*2)=lo;
                splitw(hv[ct][2],hv[ct][3],hi,lo);
                *(uu*)(smc+SM_H+(rA+8)*144+ue*2)=hi;
                *(uu*)(smc+SM_H+9216+(rA+8)*144+ue*2)=lo;
                if(wout){
                    uu rhi,rlo;
                    splitw(fmaxf(hv[ct][0],0.f),fmaxf(hv[ct][1],0.f),rhi,rlo);
                    oti[rA*36+(ue>>1)]=rhi;
                    oti[2304+rA*36+(ue>>1)]=rlo;
                    splitw(fmaxf(hv[ct][2],0.f),fmaxf(hv[ct][3],0.f),rhi,rlo);
                    oti[(rA+8)*36+(ue>>1)]=rhi;
                    oti[2304+(rA+8)*36+(ue>>1)]=rlo;
                }
            }
            if(t<31){
                uint4* xs=(uint4*)(smc+SM_X);
                #pragma unroll
                for(int j=0;j<5;++j){ int idx=tid+j*256; if(idx<TILE_U4) xs[idx]=pf[j]; }
            }
            __syncthreads();   // S2: writes visible for step t+1
        }
    }
}

// ---- fuse: W2 = soW @ s2sW, b2 = sob @ s2sW + s2sb ----------------------------
__global__ void fuse_kernel(const float* __restrict__ soW, const float* __restrict__ sob,
                            const float* __restrict__ s2sW, const float* __restrict__ s2sb)
{
    int tid=threadIdx.x;
    for(int i=tid;i<4096;i+=256){
        int k=i>>6, v=i&63;
        float a=0.f;
        for(int u=0;u<64;++u) a+=soW[k*64+u]*s2sW[u*64+v];
        d_W2[i]=a;
    }
    if(tid<64){
        float a=s2sb[tid];
        for(int u=0;u<64;++u) a+=sob[u]*s2sW[u*64+tid];
        d_b2[tid]=a;
    }
}

// ---- head: eps = relu_h31 @ W2 + b2 -> d_A, d_G --------------------------------
__global__ void __launch_bounds__(256) head_kernel()
{
    __shared__ float hs[64*65];
    int cta=blockIdx.x, tid=threadIdx.x;
    const unsigned char* th=(const unsigned char*)(d_lay[0]+(size_t)(cta*32+31)*TILE_U4);
    for(int i=tid;i<4096;i+=256){
        int m=i>>6, u=i&63;
        float v=__bfloat162float(*(const __nv_bfloat16*)(th+m*144+u*2))
               +__bfloat162float(*(const __nv_bfloat16*)(th+9216+m*144+u*2));
        hs[m*65+u]=v;
    }
    __syncthreads();
    for(int i=tid;i<4096;i+=256){
        int m=i>>6, u=i&63;
        float a=d_b2[u];
        #pragma unroll 8
        for(int k=0;k<64;++k) a+=hs[m*65+k]*__ldg(&d_W2[k*64+u]);
        int g=cta*MROWS+m;
        if(g<BS_TOT){
            if(u<HFAST) d_A[g*HFAST+u]=sigm(a);
            else        d_G[g*HFAST+u-HFAST]=a;
        }
    }
}

// ---- fast path + overlap-add (verified in R1-R4) --------------------------------
__global__ void __launch_bounds__(256) fast_kernel(
    const float* __restrict__ x, const float* __restrict__ finW,
    const float* __restrict__ finb, const float* __restrict__ foutW,
    const float* __restrict__ foutb)
{
    int w=(blockIdx.x*blockDim.x+threadIdx.x)>>5;
    int h=threadIdx.x&31;
    if(w>=BS_TOT) return;
    int b=w/NF, f=w-b*NF;
    float A=d_A[w*HFAST+h], G=d_G[w*HFAST+h];
    float fw=__ldg(&finW[h]), fb=__ldg(&finb[h]);
    float fo=__ldg(&foutW[h]), fob=__ldg(&foutb[0]);
    const float* xp=x+b*T_LEN+f*16;
    float hsv=0.f;
    #pragma unroll
    for(int t=0;t<32;++t){
        float e=(xp[t]*fw+fb)*G;
        hsv=A*hsv+e;
        float y=hsv*fo;
        #pragma unroll
        for(int mm=16;mm;mm>>=1) y+=__shfl_xor_sync(0xffffffffu,y,mm);
        if(h==t) d_S[w*32+t]=y+fob;
    }
}
__global__ void __launch_bounds__(256) oadd_kernel(float* __restrict__ out)
{
    int idx=blockIdx.x*blockDim.x+threadIdx.x;
    if(idx>=B_SZ*T_LEN) return;
    int b=idx/T_LEN, i=idx-b*T_LEN;
    int f1=i>>4, j=i&15;
    float v=0.f;
    if(f1<NF) v+=d_S[(b*NF+f1)*32+j];
    if(f1>=1) v+=d_S[(b*NF+f1-1)*32+j+16];
    out[idx]=v;
}

extern "C" void kernel_launch(void* const* d_in, const int* in_sizes, int n_in,
                              void* d_out, int out_size)
{
    const float* x    =(const float*)d_in[0];
    const float* siW  =(const float*)d_in[1];
    const float* sib  =(const float*)d_in[2];
    const float* Wih  =(const float*)d_in[3];
    const float* Whh  =(const float*)d_in[4];
    const float* bih  =(const float*)d_in[5];
    const float* bhh  =(const float*)d_in[6];
    const float* soW  =(const float*)d_in[7];
    const float* sob  =(const float*)d_in[8];
    const float* s2sW =(const float*)d_in[9];
    const float* s2sb =(const float*)d_in[10];
    const float* finW =(const float*)d_in[11];
    const float* finb =(const float*)d_in[12];
    const float* foW  =(const float*)d_in[13];
    const float* fob  =(const float*)d_in[14];
    float* out=(float*)d_out;

    cudaFuncSetAttribute(slow_kernel, cudaFuncAttributeMaxDynamicSharedMemorySize, SMEM_SZ);
    prep_kernel<<<NCTA*32,256>>>(x,siW,sib);
    fuse_kernel<<<1,256>>>(soW,sob,s2sW,s2sb);
    slow_kernel<<<NCTA,256,SMEM_SZ>>>(Wih,Whh,bih,bhh);
    head_kernel<<<NCTA,256>>>();
    fast_kernel<<<(BS_TOT*32+255)/256,256>>>(x,finW,finb,foW,fob);
    oadd_kernel<<<(B_SZ*T_LEN+255)/256,256>>>(out);
}